// round 1
// baseline (speedup 1.0000x reference)
#include <cuda_runtime.h>
#include <cuda_bf16.h>

#define NLAT_IN  181
#define NLON_IN  360
#define NLAT_OUT 361
#define NLON_OUT 720
#define KSIZE    3
#define CIN      16
#define COUT     16
#define NNZ      8192
#define MAXBUCKET 128

// Scratch (device globals: no allocation allowed in kernel_launch)
__device__ float d_xw[KSIZE * NLAT_IN * COUT * NLON_IN]; // [k][tin][o][w], 12.5 MB
__device__ int   d_meta[NNZ];    // (k<<18)|(tin<<10)|p, sorted by hi (stable)
__device__ float d_sval[NNZ];    // vals, same order
__device__ int   d_counts[NLAT_OUT];
__device__ int   d_offsets[NLAT_OUT + 1];

// ---------------------------------------------------------------------------
// 1) zero histogram
__global__ void k_zero() {
    int i = blockIdx.x * blockDim.x + threadIdx.x;
    if (i < NLAT_OUT) d_counts[i] = 0;
}

// 2) per-output-lat histogram
__global__ void k_count(const int* __restrict__ col_idx) {
    int i = blockIdx.x * blockDim.x + threadIdx.x;
    if (i < NNZ) {
        int hi = col_idx[i] / NLON_OUT;
        atomicAdd(&d_counts[hi], 1);
    }
}

// 3) exclusive scan of counts -> offsets (single block, Hillis-Steele in smem)
__global__ void k_scan() {
    __shared__ int s[512];
    int t = threadIdx.x;
    s[t] = (t < NLAT_OUT) ? d_counts[t] : 0;
    __syncthreads();
    for (int d = 1; d < 512; d <<= 1) {
        int v = (t >= d) ? s[t - d] : 0;
        __syncthreads();
        s[t] += v;
        __syncthreads();
    }
    if (t < NLAT_OUT) d_offsets[t + 1] = s[t];
    if (t == 0) d_offsets[0] = 0;
}

// 4) stable placement: one warp per output latitude bin. Warp scans all NNZ
//    entries in original order; ballot/popc gives a deterministic stable rank.
__global__ void k_place(const int* __restrict__ ker_idx,
                        const int* __restrict__ row_idx,
                        const int* __restrict__ col_idx,
                        const float* __restrict__ vals) {
    int lane = threadIdx.x & 31;
    int bin  = blockIdx.x * (blockDim.x >> 5) + (threadIdx.x >> 5);
    if (bin >= NLAT_OUT) return;
    int base = d_offsets[bin];
    int cnt = 0;
    for (int i = 0; i < NNZ; i += 32) {
        int col = col_idx[i + lane];
        int hi = col / NLON_OUT;
        unsigned m = __ballot_sync(0xffffffffu, hi == bin);
        if (hi == bin) {
            int pos = base + cnt + __popc(m & ((1u << lane) - 1u));
            int p   = col - hi * NLON_OUT;
            int k   = ker_idx[i + lane];
            int tin = row_idx[i + lane];
            d_meta[pos] = (k << 18) | (tin << 10) | p;
            d_sval[pos] = vals[i + lane];
        }
        cnt += __popc(m);
    }
}

// 5) channel-mix einsum: xw[k][tin][o][w] = sum_c x[c][tin][w] * W[o][c][k]
__global__ void k_einsum(const float* __restrict__ x,
                         const float* __restrict__ wgt) {
    __shared__ float sw[COUT * CIN * KSIZE]; // [o][c][k]
    int tin = blockIdx.x;
    int w = blockIdx.y * 128 + threadIdx.x;
    for (int i = threadIdx.x; i < COUT * CIN * KSIZE; i += 128) sw[i] = wgt[i];
    __syncthreads();
    if (w >= NLON_IN) return;

    float acc[KSIZE][COUT];
#pragma unroll
    for (int k = 0; k < KSIZE; k++)
#pragma unroll
        for (int o = 0; o < COUT; o++) acc[k][o] = 0.f;

    for (int c = 0; c < CIN; c++) {
        float xv = x[(c * NLAT_IN + tin) * NLON_IN + w];
#pragma unroll
        for (int o = 0; o < COUT; o++) {
#pragma unroll
            for (int k = 0; k < KSIZE; k++) {
                acc[k][o] += xv * sw[(o * CIN + c) * KSIZE + k];
            }
        }
    }
#pragma unroll
    for (int k = 0; k < KSIZE; k++)
#pragma unroll
        for (int o = 0; o < COUT; o++) {
            d_xw[((k * NLAT_IN + tin) * COUT + o) * NLON_IN + w] = acc[k][o];
        }
}

// 6) main gather. One block per output latitude hi. 768 threads:
//    warps 0-11 handle even lons (q=0), warps 12-23 odd lons (q=1);
//    thread jj in [0,360) owns lon = q + 2*jj for all 16 output channels
//    (register accumulators). Results staged through smem ring for fully
//    coalesced global writes.
__global__ void __launch_bounds__(768, 2)
k_main(const float* __restrict__ bias, float* __restrict__ out) {
    __shared__ float ring[COUT * NLON_OUT];   // 46080 B
    __shared__ int   smeta[MAXBUCKET];
    __shared__ float sv[MAXBUCKET];

    int hi  = blockIdx.x;
    int tid = threadIdx.x;
    int beg = d_offsets[hi];
    int cnt = d_offsets[hi + 1] - beg;
    if (cnt > MAXBUCKET) cnt = MAXBUCKET;
    if (tid < cnt) {
        smeta[tid] = d_meta[beg + tid];
        sv[tid]    = d_sval[beg + tid];
    }
    __syncthreads();

    int q  = tid / 384;          // warp-uniform parity
    int jj = tid - q * 384;

    float acc[COUT];
#pragma unroll
    for (int o = 0; o < COUT; o++) acc[o] = 0.f;

    if (jj < NLON_IN) {
        for (int e = 0; e < cnt; e++) {
            int m = smeta[e];
            int p = m & 1023;
            if ((p & 1) != q) continue;          // warp-uniform branch
            float v = sv[e];
            int tin = (m >> 10) & 255;
            int k   = m >> 18;
            int s   = (p - q) >> 1;              // shift in [0,360)
            int w   = jj - s;
            if (w < 0) w += NLON_IN;
            const float* src = d_xw + ((k * NLAT_IN + tin) * COUT) * NLON_IN + w;
#pragma unroll
            for (int o = 0; o < COUT; o++) {
                acc[o] += v * src[o * NLON_IN];  // coalesced 128B per LDG
            }
        }
        int lon = q + 2 * jj;
#pragma unroll
        for (int o = 0; o < COUT; o++) ring[o * NLON_OUT + lon] = acc[o];
    }
    __syncthreads();

    // coalesced store of the full (16 x 720) latitude slab
    for (int idx = tid; idx < COUT * NLON_OUT; idx += 768) {
        int o   = idx / NLON_OUT;
        int lon = idx - o * NLON_OUT;
        out[(o * NLAT_OUT + hi) * NLON_OUT + lon] = ring[idx] + bias[o];
    }
}

// ---------------------------------------------------------------------------
extern "C" void kernel_launch(void* const* d_in, const int* in_sizes, int n_in,
                              void* d_out, int out_size) {
    const float* x       = (const float*)d_in[0];
    const float* weight  = (const float*)d_in[1];
    const float* bias    = (const float*)d_in[2];
    const int*   ker_idx = (const int*)d_in[3];
    const int*   row_idx = (const int*)d_in[4];
    const int*   col_idx = (const int*)d_in[5];
    const float* vals    = (const float*)d_in[6];
    float* out = (float*)d_out;

    (void)in_sizes; (void)n_in; (void)out_size;

    k_zero<<<2, 256>>>();
    k_count<<<NNZ / 256, 256>>>(col_idx);
    k_scan<<<1, 512>>>();
    k_place<<<(NLAT_OUT + 7) / 8, 256>>>(ker_idx, row_idx, col_idx, vals);
    k_einsum<<<dim3(NLAT_IN, 3), 128>>>(x, weight);
    k_main<<<NLAT_OUT, 768>>>(bias, out);
}

// round 2
// speedup vs baseline: 1.0262x; 1.0262x over previous
#include <cuda_runtime.h>
#include <cuda_bf16.h>

#define NLAT_IN  181
#define NLON_IN  360
#define NLAT_OUT 361
#define NLON_OUT 720
#define KSIZE    3
#define CIN      16
#define COUT     16
#define NNZ      8192
#define NCHUNK   64
#define CHUNK    128
#define NBIN     (NLAT_OUT * 2)   // (hi, parity)
#define MAXB     128

// Scratch (device globals; allocation is forbidden in kernel_launch)
__device__ __align__(16) float d_xw[KSIZE * NLAT_IN * NLON_IN * COUT]; // [k][tin][w][o]
__device__ int   d_meta[NNZ];          // (k<<18)|(tin<<10)|s   (s = p>>1, 0..359)
__device__ float d_sval[NNZ];
__device__ int   d_chunkhist[NCHUNK * NBIN];
__device__ int   d_chunkpre [NCHUNK * NBIN];
__device__ int   d_offsets[NBIN + 1];

// ---------------------------------------------------------------------------
// 1) per-chunk histogram over 722 (lat, parity) bins
__global__ void k_hist(const int* __restrict__ col_idx) {
    __shared__ int sh[NBIN];
    int c = blockIdx.x;
    for (int i = threadIdx.x; i < NBIN; i += CHUNK) sh[i] = 0;
    __syncthreads();
    int col = col_idx[c * CHUNK + threadIdx.x];
    int hi = col / NLON_OUT;
    int p  = col - hi * NLON_OUT;
    atomicAdd(&sh[hi * 2 + (p & 1)], 1);
    __syncthreads();
    for (int i = threadIdx.x; i < NBIN; i += CHUNK) d_chunkhist[c * NBIN + i] = sh[i];
}

// 2) two-level scan: per-bin chunk prefix + cross-bin exclusive scan
__global__ void k_scan() {
    __shared__ int s[1024];
    int b = threadIdx.x;
    int total = 0;
    if (b < NBIN) {
        int run = 0;
        for (int c = 0; c < NCHUNK; c++) {
            int h = d_chunkhist[c * NBIN + b];
            d_chunkpre[c * NBIN + b] = run;
            run += h;
        }
        total = run;
    }
    s[b] = total;
    __syncthreads();
    for (int d = 1; d < 1024; d <<= 1) {
        int v = (b >= d) ? s[b - d] : 0;
        __syncthreads();
        s[b] += v;
        __syncthreads();
    }
    if (b < NBIN) d_offsets[b + 1] = s[b];
    if (b == 0) d_offsets[0] = 0;
}

// 3) stable placement: one warp per chunk, __match_any for in-round rank
__global__ void k_place(const int* __restrict__ ker_idx,
                        const int* __restrict__ row_idx,
                        const int* __restrict__ col_idx,
                        const float* __restrict__ vals) {
    __shared__ int scnt[NBIN];
    int c = blockIdx.x;
    int lane = threadIdx.x;
    for (int i = lane; i < NBIN; i += 32) scnt[i] = 0;
    __syncwarp();
    for (int r = 0; r < CHUNK / 32; r++) {
        int i   = c * CHUNK + r * 32 + lane;
        int col = col_idx[i];
        int hi  = col / NLON_OUT;
        int p   = col - hi * NLON_OUT;
        int bin = hi * 2 + (p & 1);
        unsigned match = __match_any_sync(0xffffffffu, bin);
        int rank = __popc(match & ((1u << lane) - 1u));
        int pos = d_offsets[bin] + d_chunkpre[c * NBIN + bin] + scnt[bin] + rank;
        d_meta[pos] = (ker_idx[i] << 18) | (row_idx[i] << 10) | (p >> 1);
        d_sval[pos] = vals[i];
        __syncwarp();
        if (rank == 0) scnt[bin] += __popc(match);
        __syncwarp();
    }
}

// 4) channel-mix einsum: xw[k][tin][w][o] = sum_c x[c][tin][w] * W[o][c][k]
__global__ void k_einsum(const float* __restrict__ x,
                         const float* __restrict__ wgt) {
    __shared__ float sw[COUT * CIN * KSIZE];
    int tin = blockIdx.x;
    int w = blockIdx.y * 128 + threadIdx.x;
    for (int i = threadIdx.x; i < COUT * CIN * KSIZE; i += 128) sw[i] = wgt[i];
    __syncthreads();
    if (w >= NLON_IN) return;

    float acc[KSIZE][COUT];
#pragma unroll
    for (int k = 0; k < KSIZE; k++)
#pragma unroll
        for (int o = 0; o < COUT; o++) acc[k][o] = 0.f;

    for (int c = 0; c < CIN; c++) {
        float xv = x[(c * NLAT_IN + tin) * NLON_IN + w];
#pragma unroll
        for (int o = 0; o < COUT; o++)
#pragma unroll
            for (int k = 0; k < KSIZE; k++)
                acc[k][o] += xv * sw[(o * CIN + c) * KSIZE + k];
    }
#pragma unroll
    for (int k = 0; k < KSIZE; k++) {
        float* dst = d_xw + ((k * NLAT_IN + tin) * NLON_IN + w) * COUT;
#pragma unroll
        for (int j = 0; j < 4; j++)
            ((float4*)dst)[j] = make_float4(acc[k][4 * j], acc[k][4 * j + 1],
                                            acc[k][4 * j + 2], acc[k][4 * j + 3]);
    }
}

// 5) main gather: one block per (out-lat, parity). Thread jj owns lon q+2*jj,
//    all 16 channels in float4 register accumulators; 4 x LDG.128 per entry.
__global__ void __launch_bounds__(384)
k_main(const float* __restrict__ bias, float* __restrict__ out) {
    __shared__ int   smeta[MAXB];
    __shared__ float sv[MAXB];
    int b  = blockIdx.x;
    int hi = b >> 1;
    int q  = b & 1;
    int tid = threadIdx.x;
    int beg = d_offsets[b];
    int cnt = d_offsets[b + 1] - beg;
    if (cnt > MAXB) cnt = MAXB;
    if (tid < cnt) {
        smeta[tid] = d_meta[beg + tid];
        sv[tid]    = d_sval[beg + tid];
    }
    __syncthreads();

    int jj = tid;
    if (jj >= NLON_IN) return;

    float4 a0 = make_float4(0.f, 0.f, 0.f, 0.f);
    float4 a1 = a0, a2 = a0, a3 = a0;

    for (int e = 0; e < cnt; e++) {
        int   m = smeta[e];
        float v = sv[e];
        int s   = m & 1023;
        int tin = (m >> 10) & 255;
        int k   = m >> 18;
        int w   = jj - s;
        if (w < 0) w += NLON_IN;
        const float4* src =
            (const float4*)(d_xw + ((k * NLAT_IN + tin) * NLON_IN + w) * COUT);
        float4 s0 = src[0], s1 = src[1], s2 = src[2], s3 = src[3];
        a0.x += v * s0.x; a0.y += v * s0.y; a0.z += v * s0.z; a0.w += v * s0.w;
        a1.x += v * s1.x; a1.y += v * s1.y; a1.z += v * s1.z; a1.w += v * s1.w;
        a2.x += v * s2.x; a2.y += v * s2.y; a2.z += v * s2.z; a2.w += v * s2.w;
        a3.x += v * s3.x; a3.y += v * s3.y; a3.z += v * s3.z; a3.w += v * s3.w;
    }

    int lon = q + 2 * jj;
    float* dst = out + hi * NLON_OUT + lon;
    const int cs = NLAT_OUT * NLON_OUT;
    float acc[COUT] = {a0.x, a0.y, a0.z, a0.w, a1.x, a1.y, a1.z, a1.w,
                       a2.x, a2.y, a2.z, a2.w, a3.x, a3.y, a3.z, a3.w};
#pragma unroll
    for (int o = 0; o < COUT; o++) dst[o * cs] = acc[o] + bias[o];
}

// ---------------------------------------------------------------------------
extern "C" void kernel_launch(void* const* d_in, const int* in_sizes, int n_in,
                              void* d_out, int out_size) {
    const float* x       = (const float*)d_in[0];
    const float* weight  = (const float*)d_in[1];
    const float* bias    = (const float*)d_in[2];
    const int*   ker_idx = (const int*)d_in[3];
    const int*   row_idx = (const int*)d_in[4];
    const int*   col_idx = (const int*)d_in[5];
    const float* vals    = (const float*)d_in[6];
    float* out = (float*)d_out;

    (void)in_sizes; (void)n_in; (void)out_size;

    k_hist<<<NCHUNK, CHUNK>>>(col_idx);
    k_scan<<<1, 1024>>>();
    k_place<<<NCHUNK, 32>>>(ker_idx, row_idx, col_idx, vals);
    k_einsum<<<dim3(NLAT_IN, 3), 128>>>(x, weight);
    k_main<<<NBIN, 384>>>(bias, out);
}

// round 3
// speedup vs baseline: 1.1593x; 1.1296x over previous
#include <cuda_runtime.h>
#include <cuda_fp16.h>

#define NLAT_IN  181
#define NLON_IN  360
#define NLAT_OUT 361
#define NLON_OUT 720
#define KSIZE    3
#define CIN      16
#define COUT     16
#define NNZ      8192
#define NCHUNK   64
#define CHUNK    128
#define NBIN     (NLAT_OUT * 2)   // (hi, parity)
#define MAXB     128
#define NOH      (COUT / 2)       // 8 half2 channel-pairs

// Scratch (device globals; allocation is forbidden in kernel_launch)
__device__ __half2 d_xwh[KSIZE * NLAT_IN * NOH * NLON_IN]; // [k][tin][oh][w], 6.25 MB
__device__ int   d_meta[NNZ];          // (k<<18)|(tin<<10)|s   (s = p>>1)
__device__ float d_sval[NNZ];
__device__ int   d_chunkhist[NBIN * NCHUNK];  // [bin][chunk] (transposed)
__device__ int   d_chunkpre [NCHUNK * NBIN];  // [chunk][bin]
__device__ int   d_offsets[NBIN + 1];

// ---------------------------------------------------------------------------
// 1) per-chunk histogram over 722 (lat, parity) bins
__global__ void k_hist(const int* __restrict__ col_idx) {
    __shared__ int sh[NBIN];
    int c = blockIdx.x;
    for (int i = threadIdx.x; i < NBIN; i += CHUNK) sh[i] = 0;
    __syncthreads();
    int col = col_idx[c * CHUNK + threadIdx.x];
    int hi = col / NLON_OUT;
    int p  = col - hi * NLON_OUT;
    atomicAdd(&sh[hi * 2 + (p & 1)], 1);
    __syncthreads();
    for (int i = threadIdx.x; i < NBIN; i += CHUNK)
        d_chunkhist[i * NCHUNK + c] = sh[i];
}

// 2) two-level scan: per-bin chunk prefix + cross-bin exclusive scan
__global__ void k_scan() {
    __shared__ int s[1024];
    int b = threadIdx.x;
    int total = 0;
    if (b < NBIN) {
        int run = 0;
#pragma unroll 8
        for (int c = 0; c < NCHUNK; c++) {
            int h = d_chunkhist[b * NCHUNK + c];   // contiguous per thread
            d_chunkpre[c * NBIN + b] = run;
            run += h;
        }
        total = run;
    }
    s[b] = total;
    __syncthreads();
    for (int d = 1; d < 1024; d <<= 1) {
        int v = (b >= d) ? s[b - d] : 0;
        __syncthreads();
        s[b] += v;
        __syncthreads();
    }
    if (b < NBIN) d_offsets[b + 1] = s[b];
    if (b == 0) d_offsets[0] = 0;
}

// 3) stable placement: one warp per chunk, __match_any for in-round rank
__global__ void k_place(const int* __restrict__ ker_idx,
                        const int* __restrict__ row_idx,
                        const int* __restrict__ col_idx,
                        const float* __restrict__ vals) {
    __shared__ int scnt[NBIN];
    int c = blockIdx.x;
    int lane = threadIdx.x;
    for (int i = lane; i < NBIN; i += 32) scnt[i] = 0;
    __syncwarp();
    for (int r = 0; r < CHUNK / 32; r++) {
        int i   = c * CHUNK + r * 32 + lane;
        int col = col_idx[i];
        int hi  = col / NLON_OUT;
        int p   = col - hi * NLON_OUT;
        int bin = hi * 2 + (p & 1);
        unsigned match = __match_any_sync(0xffffffffu, bin);
        int rank = __popc(match & ((1u << lane) - 1u));
        int pos = d_offsets[bin] + d_chunkpre[c * NBIN + bin] + scnt[bin] + rank;
        d_meta[pos] = (ker_idx[i] << 18) | (row_idx[i] << 10) | (p >> 1);
        d_sval[pos] = vals[i];
        __syncwarp();
        if (rank == 0) scnt[bin] += __popc(match);
        __syncwarp();
    }
}

// 4) channel-mix einsum: xw[k][tin][oh][w] (half2) = sum_c x[c][tin][w]*W[o][c][k]
//    k-outer register blocking: only 16 live accumulators at a time.
__global__ void __launch_bounds__(384)
k_einsum(const float* __restrict__ x, const float* __restrict__ wgt) {
    __shared__ float sw[COUT * CIN * KSIZE]; // [o][c][k]
    int tin = blockIdx.x;
    int w = threadIdx.x;
    for (int i = threadIdx.x; i < COUT * CIN * KSIZE; i += 384) sw[i] = wgt[i];
    __syncthreads();
    if (w >= NLON_IN) return;

    float xv[CIN];
#pragma unroll
    for (int c = 0; c < CIN; c++)
        xv[c] = x[(c * NLAT_IN + tin) * NLON_IN + w];

#pragma unroll
    for (int k = 0; k < KSIZE; k++) {
        float acc[COUT];
#pragma unroll
        for (int o = 0; o < COUT; o++) acc[o] = 0.f;
#pragma unroll
        for (int c = 0; c < CIN; c++) {
            float xc = xv[c];
#pragma unroll
            for (int o = 0; o < COUT; o++)
                acc[o] += xc * sw[(o * CIN + c) * KSIZE + k];
        }
        __half2* dst = d_xwh + ((k * NLAT_IN + tin) * NOH) * NLON_IN + w;
#pragma unroll
        for (int oh = 0; oh < NOH; oh++)
            dst[oh * NLON_IN] = __floats2half2_rn(acc[2 * oh], acc[2 * oh + 1]);
    }
}

// 5) main gather: one block per (out-lat, parity). Thread jj owns lon q+2*jj.
//    Per entry: 8 coalesced half2 loads (128B/warp each), fp32 accumulate.
__global__ void __launch_bounds__(384)
k_main(const float* __restrict__ bias, float* __restrict__ out) {
    __shared__ int   smeta[MAXB];
    __shared__ float sv[MAXB];
    int b  = blockIdx.x;
    int hi = b >> 1;
    int q  = b & 1;
    int tid = threadIdx.x;
    int beg = d_offsets[b];
    int cnt = d_offsets[b + 1] - beg;
    if (cnt > MAXB) cnt = MAXB;
    if (tid < cnt) {
        smeta[tid] = d_meta[beg + tid];
        sv[tid]    = d_sval[beg + tid];
    }
    __syncthreads();

    int jj = tid;
    if (jj >= NLON_IN) return;

    float acc[COUT];
#pragma unroll
    for (int o = 0; o < COUT; o++) acc[o] = 0.f;

    for (int e = 0; e < cnt; e++) {
        int   m = smeta[e];
        float v = sv[e];
        int s   = m & 1023;
        int tin = (m >> 10) & 255;
        int k   = m >> 18;
        int w   = jj - s;
        if (w < 0) w += NLON_IN;
        const __half2* src = d_xwh + ((k * NLAT_IN + tin) * NOH) * NLON_IN + w;
#pragma unroll
        for (int oh = 0; oh < NOH; oh++) {
            float2 t = __half22float2(src[oh * NLON_IN]);
            acc[2 * oh]     += v * t.x;
            acc[2 * oh + 1] += v * t.y;
        }
    }

    int lon = q + 2 * jj;
    float* dst = out + hi * NLON_OUT + lon;
    const int cs = NLAT_OUT * NLON_OUT;
#pragma unroll
    for (int o = 0; o < COUT; o++) dst[o * cs] = acc[o] + bias[o];
}

// ---------------------------------------------------------------------------
extern "C" void kernel_launch(void* const* d_in, const int* in_sizes, int n_in,
                              void* d_out, int out_size) {
    const float* x       = (const float*)d_in[0];
    const float* weight  = (const float*)d_in[1];
    const float* bias    = (const float*)d_in[2];
    const int*   ker_idx = (const int*)d_in[3];
    const int*   row_idx = (const int*)d_in[4];
    const int*   col_idx = (const int*)d_in[5];
    const float* vals    = (const float*)d_in[6];
    float* out = (float*)d_out;

    (void)in_sizes; (void)n_in; (void)out_size;

    k_hist<<<NCHUNK, CHUNK>>>(col_idx);
    k_scan<<<1, 1024>>>();
    k_place<<<NCHUNK, 32>>>(ker_idx, row_idx, col_idx, vals);
    k_einsum<<<NLAT_IN, 384>>>(x, weight);
    k_main<<<NBIN, 384>>>(bias, out);
}

// round 4
// speedup vs baseline: 1.1660x; 1.0059x over previous
#include <cuda_runtime.h>
#include <cuda_fp16.h>

#define NLAT_IN  181
#define NLON_IN  360
#define NLAT_OUT 361
#define NLON_OUT 720
#define KSIZE    3
#define CIN      16
#define COUT     16
#define NNZ      8192
#define NCHUNK   64
#define CHUNK    128
#define NBIN     (NLAT_OUT * 2)   // (hi, parity)
#define MAXB     128
#define NOH      (COUT / 2)       // 8 half2 channel-pairs

// Scratch (device globals; allocation is forbidden in kernel_launch)
__device__ __half2 d_xwh[KSIZE * NLAT_IN * NOH * NLON_IN]; // [k][tin][oh][w], 6.25 MB
__device__ int   d_meta[NNZ];          // (k<<18)|(tin<<10)|s   (s = p>>1)
__device__ float d_sval[NNZ];
__device__ int   d_chunkhist[NBIN * NCHUNK];  // [bin][chunk] (transposed)
__device__ int   d_chunkpre [NCHUNK * NBIN];  // [chunk][bin]
__device__ int   d_offsets[NBIN + 1];

// ---------------------------------------------------------------------------
// 1) per-chunk histogram over 722 (lat, parity) bins
__global__ void k_hist(const int* __restrict__ col_idx) {
    __shared__ int sh[NBIN];
    int c = blockIdx.x;
    for (int i = threadIdx.x; i < NBIN; i += CHUNK) sh[i] = 0;
    __syncthreads();
    int col = col_idx[c * CHUNK + threadIdx.x];
    int hi = col / NLON_OUT;
    int p  = col - hi * NLON_OUT;
    atomicAdd(&sh[hi * 2 + (p & 1)], 1);
    __syncthreads();
    for (int i = threadIdx.x; i < NBIN; i += CHUNK)
        d_chunkhist[i * NCHUNK + c] = sh[i];
}

// 2) two-level scan: per-bin chunk prefix + cross-bin exclusive scan
__global__ void k_scan() {
    __shared__ int s[1024];
    int b = threadIdx.x;
    int total = 0;
    if (b < NBIN) {
        int run = 0;
#pragma unroll 16
        for (int c = 0; c < NCHUNK; c++) {
            int h = d_chunkhist[b * NCHUNK + c];   // contiguous per thread
            d_chunkpre[c * NBIN + b] = run;
            run += h;
        }
        total = run;
    }
    s[b] = total;
    __syncthreads();
    for (int d = 1; d < 1024; d <<= 1) {
        int v = (b >= d) ? s[b - d] : 0;
        __syncthreads();
        s[b] += v;
        __syncthreads();
    }
    if (b < NBIN) d_offsets[b + 1] = s[b];
    if (b == 0) d_offsets[0] = 0;
}

// 3) stable placement: one warp per chunk, __match_any for in-round rank
__global__ void k_place(const int* __restrict__ ker_idx,
                        const int* __restrict__ row_idx,
                        const int* __restrict__ col_idx,
                        const float* __restrict__ vals) {
    __shared__ int scnt[NBIN];
    int c = blockIdx.x;
    int lane = threadIdx.x;
    for (int i = lane; i < NBIN; i += 32) scnt[i] = 0;
    __syncwarp();
    for (int r = 0; r < CHUNK / 32; r++) {
        int i   = c * CHUNK + r * 32 + lane;
        int col = col_idx[i];
        int hi  = col / NLON_OUT;
        int p   = col - hi * NLON_OUT;
        int bin = hi * 2 + (p & 1);
        unsigned match = __match_any_sync(0xffffffffu, bin);
        int rank = __popc(match & ((1u << lane) - 1u));
        int pos = d_offsets[bin] + d_chunkpre[c * NBIN + bin] + scnt[bin] + rank;
        d_meta[pos] = (ker_idx[i] << 18) | (row_idx[i] << 10) | (p >> 1);
        d_sval[pos] = vals[i];
        __syncwarp();
        if (rank == 0) scnt[bin] += __popc(match);
        __syncwarp();
    }
}

// 4) channel-mix einsum, one block per (tin, k): only 16 live accumulators,
//    weights for this k staged in smem. xw[k][tin][oh][w] (half2).
__global__ void __launch_bounds__(384)
k_einsum(const float* __restrict__ x, const float* __restrict__ wgt) {
    __shared__ float sw[COUT * CIN];  // [o][c] for this k
    int tin = blockIdx.x;
    int k   = blockIdx.y;
    int t   = threadIdx.x;
    if (t < COUT * CIN) sw[t] = wgt[t * KSIZE + k];  // wgt[o][c][k]
    __syncthreads();
    int w = t;
    if (w >= NLON_IN) return;

    float acc[COUT];
#pragma unroll
    for (int o = 0; o < COUT; o++) acc[o] = 0.f;

#pragma unroll
    for (int c = 0; c < CIN; c++) {
        float xc = x[(c * NLAT_IN + tin) * NLON_IN + w];
#pragma unroll
        for (int o = 0; o < COUT; o++)
            acc[o] += xc * sw[o * CIN + c];
    }
    __half2* dst = d_xwh + ((k * NLAT_IN + tin) * NOH) * NLON_IN + w;
#pragma unroll
    for (int oh = 0; oh < NOH; oh++)
        dst[oh * NLON_IN] = __floats2half2_rn(acc[2 * oh], acc[2 * oh + 1]);
}

// 5) main gather: one block per (out-lat, parity). Thread jj owns lon q+2*jj.
//    Entry loop unrolled x2: 16 independent coalesced half2 loads in flight.
__global__ void __launch_bounds__(384)
k_main(const float* __restrict__ bias, float* __restrict__ out) {
    __shared__ int   smeta[MAXB];
    __shared__ float sv[MAXB];
    int b  = blockIdx.x;
    int hi = b >> 1;
    int q  = b & 1;
    int tid = threadIdx.x;
    int beg = d_offsets[b];
    int cnt = d_offsets[b + 1] - beg;
    if (cnt > MAXB) cnt = MAXB;
    if (tid < cnt) {
        smeta[tid] = d_meta[beg + tid];
        sv[tid]    = d_sval[beg + tid];
    }
    __syncthreads();

    int jj = tid;
    if (jj >= NLON_IN) return;

    float acc[COUT];
#pragma unroll
    for (int o = 0; o < COUT; o++) acc[o] = 0.f;

    int e = 0;
    for (; e + 1 < cnt; e += 2) {
        int   mA = smeta[e],     mB = smeta[e + 1];
        float vA = sv[e],        vB = sv[e + 1];
        int sA = mA & 1023,      sB = mB & 1023;
        int tinA = (mA >> 10) & 255, tinB = (mB >> 10) & 255;
        int kA = mA >> 18,       kB = mB >> 18;
        int wA = jj - sA; if (wA < 0) wA += NLON_IN;
        int wB = jj - sB; if (wB < 0) wB += NLON_IN;
        const __half2* pA = d_xwh + ((kA * NLAT_IN + tinA) * NOH) * NLON_IN + wA;
        const __half2* pB = d_xwh + ((kB * NLAT_IN + tinB) * NOH) * NLON_IN + wB;
        __half2 ra[NOH], rb[NOH];
#pragma unroll
        for (int oh = 0; oh < NOH; oh++) { ra[oh] = pA[oh * NLON_IN]; }
#pragma unroll
        for (int oh = 0; oh < NOH; oh++) { rb[oh] = pB[oh * NLON_IN]; }
#pragma unroll
        for (int oh = 0; oh < NOH; oh++) {
            float2 ta = __half22float2(ra[oh]);
            float2 tb = __half22float2(rb[oh]);
            acc[2 * oh]     += vA * ta.x + vB * tb.x;
            acc[2 * oh + 1] += vA * ta.y + vB * tb.y;
        }
    }
    if (e < cnt) {
        int   m = smeta[e];
        float v = sv[e];
        int s   = m & 1023;
        int tin = (m >> 10) & 255;
        int k   = m >> 18;
        int w   = jj - s; if (w < 0) w += NLON_IN;
        const __half2* src = d_xwh + ((k * NLAT_IN + tin) * NOH) * NLON_IN + w;
#pragma unroll
        for (int oh = 0; oh < NOH; oh++) {
            float2 t = __half22float2(src[oh * NLON_IN]);
            acc[2 * oh]     += v * t.x;
            acc[2 * oh + 1] += v * t.y;
        }
    }

    int lon = q + 2 * jj;
    float* dst = out + hi * NLON_OUT + lon;
    const int cs = NLAT_OUT * NLON_OUT;
#pragma unroll
    for (int o = 0; o < COUT; o++) dst[o * cs] = acc[o] + bias[o];
}

// ---------------------------------------------------------------------------
extern "C" void kernel_launch(void* const* d_in, const int* in_sizes, int n_in,
                              void* d_out, int out_size) {
    const float* x       = (const float*)d_in[0];
    const float* weight  = (const float*)d_in[1];
    const float* bias    = (const float*)d_in[2];
    const int*   ker_idx = (const int*)d_in[3];
    const int*   row_idx = (const int*)d_in[4];
    const int*   col_idx = (const int*)d_in[5];
    const float* vals    = (const float*)d_in[6];
    float* out = (float*)d_out;

    (void)in_sizes; (void)n_in; (void)out_size;

    k_einsum<<<dim3(NLAT_IN, KSIZE), 384>>>(x, weight);
    k_hist<<<NCHUNK, CHUNK>>>(col_idx);
    k_scan<<<1, 1024>>>();
    k_place<<<NCHUNK, 32>>>(ker_idx, row_idx, col_idx, vals);
    k_main<<<NBIN, 384>>>(bias, out);
}

// round 5
// speedup vs baseline: 1.4734x; 1.2636x over previous
#include <cuda_runtime.h>
#include <cuda_fp16.h>

#define NLAT_IN  181
#define NLON_IN  360
#define NLAT_OUT 361
#define NLON_OUT 720
#define KSIZE    3
#define CIN      16
#define COUT     16
#define NNZ      8192
#define NBIN     (NLAT_OUT * 2)   // (hi, parity)
#define MAXB     128
#define NOH      (COUT / 2)       // 8 half2 channel-pairs
#define NWARP    32
#define SORT_SMEM ((NWARP * NBIN + 1024) * 4)

// Scratch (device globals; allocation is forbidden in kernel_launch)
__device__ __half2 d_xwh[KSIZE * NLAT_IN * NOH * NLON_IN]; // [k][tin][oh][w], 6.25 MB
__device__ int   d_meta[NNZ];          // (k<<18)|(tin<<10)|s   (s = p>>1)
__device__ float d_sval[NNZ];
__device__ int   d_offsets[NBIN + 1];

// ---------------------------------------------------------------------------
// Fused stable counting sort over 722 (lat, parity) bins. ONE block,
// 1024 threads = 32 warps; warp w owns elements [w*256, (w+1)*256).
__global__ void __launch_bounds__(1024)
k_sort(const int* __restrict__ ker_idx, const int* __restrict__ row_idx,
       const int* __restrict__ col_idx, const float* __restrict__ vals) {
    extern __shared__ int swh[];          // [32][NBIN] per-warp counts, then [1024] scan
    int* s = swh + NWARP * NBIN;

    int t = threadIdx.x;
    int w = t >> 5;
    int lane = t & 31;

    for (int i = t; i < NWARP * NBIN; i += 1024) swh[i] = 0;
    __syncthreads();

    // Phase 1: per-warp stable ranks (8 rounds of 32 elements)
    int bins[8], ranks[8], metas[8];
    float vls[8];
#pragma unroll
    for (int r = 0; r < 8; r++) {
        int i   = w * 256 + r * 32 + lane;
        int col = col_idx[i];
        int hi  = col / NLON_OUT;
        int p   = col - hi * NLON_OUT;
        int bin = hi * 2 + (p & 1);
        metas[r] = (ker_idx[i] << 18) | (row_idx[i] << 10) | (p >> 1);
        vls[r]   = vals[i];
        unsigned match = __match_any_sync(0xffffffffu, bin);
        int rl   = __popc(match & ((1u << lane) - 1u));
        int base = swh[w * NBIN + bin];
        bins[r]  = bin;
        ranks[r] = base + rl;
        __syncwarp();
        if (rl == 0) swh[w * NBIN + bin] = base + __popc(match);
        __syncwarp();
    }
    __syncthreads();

    // Phase 2: per-bin warp prefix + cross-bin exclusive scan
    int total = 0;
    if (t < NBIN) {
        int run = 0;
#pragma unroll 8
        for (int ww = 0; ww < NWARP; ww++) {
            int v = swh[ww * NBIN + t];
            swh[ww * NBIN + t] = run;   // per-warp prefix (within bin)
            run += v;
        }
        total = run;
    }
    s[t] = total;
    __syncthreads();
    for (int d = 1; d < 1024; d <<= 1) {
        int v = (t >= d) ? s[t - d] : 0;
        __syncthreads();
        s[t] += v;
        __syncthreads();
    }
    if (t < NBIN) {
        int excl = s[t] - total;
        d_offsets[t] = excl;
        if (t == NBIN - 1) d_offsets[NBIN] = excl + total;
#pragma unroll 8
        for (int ww = 0; ww < NWARP; ww++) swh[ww * NBIN + t] += excl;
    }
    __syncthreads();

    // Phase 3: scatter
#pragma unroll
    for (int r = 0; r < 8; r++) {
        int pos = swh[w * NBIN + bins[r]] + ranks[r];
        d_meta[pos] = metas[r];
        d_sval[pos] = vls[r];
    }
}

// ---------------------------------------------------------------------------
// channel-mix einsum, one block per (tin, k): 16 live accumulators,
// weights for this k staged in smem. xw[k][tin][oh][w] (half2).
__global__ void __launch_bounds__(384)
k_einsum(const float* __restrict__ x, const float* __restrict__ wgt) {
    __shared__ float sw[COUT * CIN];  // [o][c] for this k
    int tin = blockIdx.x;
    int k   = blockIdx.y;
    int t   = threadIdx.x;
    if (t < COUT * CIN) sw[t] = wgt[t * KSIZE + k];  // wgt[o][c][k]
    __syncthreads();
    int w = t;
    if (w >= NLON_IN) return;

    float acc[COUT];
#pragma unroll
    for (int o = 0; o < COUT; o++) acc[o] = 0.f;

#pragma unroll
    for (int c = 0; c < CIN; c++) {
        float xc = x[(c * NLAT_IN + tin) * NLON_IN + w];
#pragma unroll
        for (int o = 0; o < COUT; o++)
            acc[o] += xc * sw[o * CIN + c];
    }
    __half2* dst = d_xwh + ((k * NLAT_IN + tin) * NOH) * NLON_IN + w;
#pragma unroll
    for (int oh = 0; oh < NOH; oh++)
        dst[oh * NLON_IN] = __floats2half2_rn(acc[2 * oh], acc[2 * oh + 1]);
}

// ---------------------------------------------------------------------------
// main gather: one block per (out-lat, parity). Thread jj owns lon q+2*jj.
// Entry loop unrolled x2: 16 independent coalesced half2 loads in flight.
__global__ void __launch_bounds__(384)
k_main(const float* __restrict__ bias, float* __restrict__ out) {
    __shared__ int   smeta[MAXB];
    __shared__ float sv[MAXB];
    int b  = blockIdx.x;
    int hi = b >> 1;
    int q  = b & 1;
    int tid = threadIdx.x;
    int beg = d_offsets[b];
    int cnt = d_offsets[b + 1] - beg;
    if (cnt > MAXB) cnt = MAXB;
    if (tid < cnt) {
        smeta[tid] = d_meta[beg + tid];
        sv[tid]    = d_sval[beg + tid];
    }
    __syncthreads();

    int jj = tid;
    if (jj >= NLON_IN) return;

    float acc[COUT];
#pragma unroll
    for (int o = 0; o < COUT; o++) acc[o] = 0.f;

    int e = 0;
    for (; e + 1 < cnt; e += 2) {
        int   mA = smeta[e],     mB = smeta[e + 1];
        float vA = sv[e],        vB = sv[e + 1];
        int sA = mA & 1023,      sB = mB & 1023;
        int tinA = (mA >> 10) & 255, tinB = (mB >> 10) & 255;
        int kA = mA >> 18,       kB = mB >> 18;
        int wA = jj - sA; if (wA < 0) wA += NLON_IN;
        int wB = jj - sB; if (wB < 0) wB += NLON_IN;
        const __half2* pA = d_xwh + ((kA * NLAT_IN + tinA) * NOH) * NLON_IN + wA;
        const __half2* pB = d_xwh + ((kB * NLAT_IN + tinB) * NOH) * NLON_IN + wB;
        __half2 ra[NOH], rb[NOH];
#pragma unroll
        for (int oh = 0; oh < NOH; oh++) { ra[oh] = pA[oh * NLON_IN]; }
#pragma unroll
        for (int oh = 0; oh < NOH; oh++) { rb[oh] = pB[oh * NLON_IN]; }
#pragma unroll
        for (int oh = 0; oh < NOH; oh++) {
            float2 ta = __half22float2(ra[oh]);
            float2 tb = __half22float2(rb[oh]);
            acc[2 * oh]     += vA * ta.x + vB * tb.x;
            acc[2 * oh + 1] += vA * ta.y + vB * tb.y;
        }
    }
    if (e < cnt) {
        int   m = smeta[e];
        float v = sv[e];
        int s   = m & 1023;
        int tin = (m >> 10) & 255;
        int k   = m >> 18;
        int w   = jj - s; if (w < 0) w += NLON_IN;
        const __half2* src = d_xwh + ((k * NLAT_IN + tin) * NOH) * NLON_IN + w;
#pragma unroll
        for (int oh = 0; oh < NOH; oh++) {
            float2 t = __half22float2(src[oh * NLON_IN]);
            acc[2 * oh]     += v * t.x;
            acc[2 * oh + 1] += v * t.y;
        }
    }

    int lon = q + 2 * jj;
    float* dst = out + hi * NLON_OUT + lon;
    const int cs = NLAT_OUT * NLON_OUT;
#pragma unroll
    for (int o = 0; o < COUT; o++) dst[o * cs] = acc[o] + bias[o];
}

// ---------------------------------------------------------------------------
extern "C" void kernel_launch(void* const* d_in, const int* in_sizes, int n_in,
                              void* d_out, int out_size) {
    const float* x       = (const float*)d_in[0];
    const float* weight  = (const float*)d_in[1];
    const float* bias    = (const float*)d_in[2];
    const int*   ker_idx = (const int*)d_in[3];
    const int*   row_idx = (const int*)d_in[4];
    const int*   col_idx = (const int*)d_in[5];
    const float* vals    = (const float*)d_in[6];
    float* out = (float*)d_out;

    (void)in_sizes; (void)n_in; (void)out_size;

    cudaFuncSetAttribute(k_sort, cudaFuncAttributeMaxDynamicSharedMemorySize,
                         SORT_SMEM);
    k_einsum<<<dim3(NLAT_IN, KSIZE), 384>>>(x, weight);
    k_sort<<<1, 1024, SORT_SMEM>>>(ker_idx, row_idx, col_idx, vals);
    k_main<<<NBIN, 384>>>(bias, out);
}

// round 7
// speedup vs baseline: 1.5506x; 1.0524x over previous
#include <cuda_runtime.h>
#include <cuda_fp16.h>

#define NLAT_IN  181
#define NLON_IN  360
#define NLAT_OUT 361
#define NLON_OUT 720
#define KSIZE    3
#define CIN      16
#define COUT     16
#define NNZ      8192
#define NBIN     (NLAT_OUT * 2)   // (hi, parity)
#define MAXB     128
#define NOH      (COUT / 2)       // 8 half2 channel-pairs
#define NWS      16               // sort warps
#define EPW      (NNZ / NWS)      // 512 elements per sort warp
#define NEIN     (NLAT_IN * KSIZE)       // 543 einsum blocks
#define SORT_SMEM ((NWS * NBIN + 768) * 4)

// Scratch (device globals; allocation is forbidden in kernel_launch)
__device__ __half2 d_xwh[KSIZE * NLAT_IN * NOH * NLON_IN]; // [k][tin][oh][w], 6.25 MB
__device__ int   d_meta[NNZ];          // (k<<18)|(tin<<10)|s   (s = p>>1)
__device__ float d_sval[NNZ];
__device__ int   d_pack[NNZ];          // bin<<16 | warp-local stable rank
__device__ int   d_offsets[NBIN + 1];

// ---------------------------------------------------------------------------
// Fused: blocks 0..542 do the channel-mix einsum; block 543 does the full
// stable counting sort (16 worker warps, 768 threads for the 722-bin scan).
__global__ void __launch_bounds__(768)
k_prep(const float* __restrict__ x, const float* __restrict__ wgt,
       const int* __restrict__ ker_idx, const int* __restrict__ row_idx,
       const int* __restrict__ col_idx, const float* __restrict__ vals) {
    int t = threadIdx.x;

    if (blockIdx.x == NEIN) {
        // ---------------- sort path ----------------
        extern __shared__ int swh[];      // [NWS][NBIN] counts, then [768] scan
        int* s = swh + NWS * NBIN;
        int w = t >> 5, lane = t & 31;

        for (int i = t; i < NWS * NBIN; i += 768) swh[i] = 0;
        __syncthreads();

        // Phase 1: per-warp stable ranks; spill (bin, rank) to d_pack
        if (w < NWS) {
            for (int r = 0; r < EPW / 32; r++) {
                int i   = w * EPW + r * 32 + lane;
                int col = col_idx[i];
                int hi  = col / NLON_OUT;
                int p   = col - hi * NLON_OUT;
                int bin = hi * 2 + (p & 1);
                unsigned match = __match_any_sync(0xffffffffu, bin);
                int rl   = __popc(match & ((1u << lane) - 1u));
                int base = swh[w * NBIN + bin];
                d_pack[i] = (bin << 16) | (base + rl);
                __syncwarp();
                if (rl == 0) swh[w * NBIN + bin] = base + __popc(match);
                __syncwarp();
            }
        }
        __syncthreads();

        // Phase 2: per-bin warp prefix + cross-bin exclusive scan
        int total = 0;
        if (t < NBIN) {
            int run = 0;
#pragma unroll
            for (int ww = 0; ww < NWS; ww++) {
                int v = swh[ww * NBIN + t];
                swh[ww * NBIN + t] = run;
                run += v;
            }
            total = run;
        }
        s[t] = total;
        __syncthreads();
        for (int d = 1; d < 768; d <<= 1) {
            int v = (t >= d) ? s[t - d] : 0;
            __syncthreads();
            s[t] += v;
            __syncthreads();
        }
        if (t < NBIN) {
            int excl = s[t] - total;
            d_offsets[t] = excl;
            if (t == NBIN - 1) d_offsets[NBIN] = excl + total;
#pragma unroll
            for (int ww = 0; ww < NWS; ww++) swh[ww * NBIN + t] += excl;
        }
        __syncthreads();

        // Phase 3: scatter (recompute meta from L2-resident inputs)
        if (w < NWS) {
            for (int r = 0; r < EPW / 32; r++) {
                int i    = w * EPW + r * 32 + lane;
                int pk   = d_pack[i];
                int bin  = pk >> 16;
                int rank = pk & 0xffff;
                int col  = col_idx[i];
                int hi   = col / NLON_OUT;
                int p    = col - hi * NLON_OUT;
                int pos  = swh[w * NBIN + bin] + rank;
                d_meta[pos] = (ker_idx[i] << 18) | (row_idx[i] << 10) | (p >> 1);
                d_sval[pos] = vals[i];
            }
        }
        return;
    }

    // ---------------- einsum path ----------------
    // block b: tin = b % 181, k = b / 181. Threads split: h=0 handles
    // channels 0..7 (t in [0,384)), h=1 handles channels 8..15.
    __shared__ float sw[COUT * CIN];  // [o][c] for this k
    int b   = blockIdx.x;
    int tin = b % NLAT_IN;
    int k   = b / NLAT_IN;
    if (t < COUT * CIN) sw[t] = wgt[t * KSIZE + k];  // wgt[o][c][k]
    __syncthreads();

    int h = (t >= 384) ? 1 : 0;
    int w = t - h * 384;
    if (w >= NLON_IN) return;

    float acc[8];
#pragma unroll
    for (int o = 0; o < 8; o++) acc[o] = 0.f;

#pragma unroll
    for (int c = 0; c < CIN; c++) {
        float xc = x[(c * NLAT_IN + tin) * NLON_IN + w];
#pragma unroll
        for (int o = 0; o < 8; o++)
            acc[o] += xc * sw[(h * 8 + o) * CIN + c];
    }
    __half2* dst = d_xwh + ((k * NLAT_IN + tin) * NOH + h * 4) * NLON_IN + w;
#pragma unroll
    for (int oh = 0; oh < 4; oh++)
        dst[oh * NLON_IN] = __floats2half2_rn(acc[2 * oh], acc[2 * oh + 1]);
}

// ---------------------------------------------------------------------------
// main gather: one block per (out-lat, parity). Thread jj owns lon q+2*jj.
__global__ void __launch_bounds__(384)
k_main(const float* __restrict__ bias, float* __restrict__ out) {
    __shared__ int   smeta[MAXB];
    __shared__ float sv[MAXB];
    int b  = blockIdx.x;
    int hi = b >> 1;
    int q  = b & 1;
    int tid = threadIdx.x;
    int beg = d_offsets[b];
    int cnt = d_offsets[b + 1] - beg;
    if (cnt > MAXB) cnt = MAXB;
    if (tid < cnt) {
        smeta[tid] = d_meta[beg + tid];
        sv[tid]    = d_sval[beg + tid];
    }
    __syncthreads();

    int jj = tid;
    if (jj >= NLON_IN) return;

    float acc[COUT];
#pragma unroll
    for (int o = 0; o < COUT; o++) acc[o] = 0.f;

    int e = 0;
    for (; e + 1 < cnt; e += 2) {
        int   mA = smeta[e],     mB = smeta[e + 1];
        float vA = sv[e],        vB = sv[e + 1];
        int sA = mA & 1023,      sB = mB & 1023;
        int tinA = (mA >> 10) & 255, tinB = (mB >> 10) & 255;
        int kA = mA >> 18,       kB = mB >> 18;
        int wA = jj - sA; if (wA < 0) wA += NLON_IN;
        int wB = jj - sB; if (wB < 0) wB += NLON_IN;
        const __half2* pA = d_xwh + ((kA * NLAT_IN + tinA) * NOH) * NLON_IN + wA;
        const __half2* pB = d_xwh + ((kB * NLAT_IN + tinB) * NOH) * NLON_IN + wB;
        __half2 ra[NOH], rb[NOH];
#pragma unroll
        for (int oh = 0; oh < NOH; oh++) { ra[oh] = pA[oh * NLON_IN]; }
#pragma unroll
        for (int oh = 0; oh < NOH; oh++) { rb[oh] = pB[oh * NLON_IN]; }
#pragma unroll
        for (int oh = 0; oh < NOH; oh++) {
            float2 ta = __half22float2(ra[oh]);
            float2 tb = __half22float2(rb[oh]);
            acc[2 * oh]     += vA * ta.x + vB * tb.x;
            acc[2 * oh + 1] += vA * ta.y + vB * tb.y;
        }
    }
    if (e < cnt) {
        int   m = smeta[e];
        float v = sv[e];
        int s   = m & 1023;
        int tin = (m >> 10) & 255;
        int k   = m >> 18;
        int w   = jj - s; if (w < 0) w += NLON_IN;
        const __half2* src = d_xwh + ((k * NLAT_IN + tin) * NOH) * NLON_IN + w;
#pragma unroll
        for (int oh = 0; oh < NOH; oh++) {
            float2 t = __half22float2(src[oh * NLON_IN]);
            acc[2 * oh]     += v * t.x;
            acc[2 * oh + 1] += v * t.y;
        }
    }

    int lon = q + 2 * jj;
    float* dst = out + hi * NLON_OUT + lon;
    const int cs = NLAT_OUT * NLON_OUT;
#pragma unroll
    for (int o = 0; o < COUT; o++) dst[o * cs] = acc[o] + bias[o];
}

// ---------------------------------------------------------------------------
extern "C" void kernel_launch(void* const* d_in, const int* in_sizes, int n_in,
                              void* d_out, int out_size) {
    const float* x       = (const float*)d_in[0];
    const float* weight  = (const float*)d_in[1];
    const float* bias    = (const float*)d_in[2];
    const int*   ker_idx = (const int*)d_in[3];
    const int*   row_idx = (const int*)d_in[4];
    const int*   col_idx = (const int*)d_in[5];
    const float* vals    = (const float*)d_in[6];
    float* out = (float*)d_out;

    (void)in_sizes; (void)n_in; (void)out_size;

    cudaFuncSetAttribute(k_prep, cudaFuncAttributeMaxDynamicSharedMemorySize,
                         SORT_SMEM);
    k_prep<<<NEIN + 1, 768, SORT_SMEM>>>(x, weight, ker_idx, row_idx,
                                         col_idx, vals);
    k_main<<<NBIN, 384>>>(bias, out);
}

// round 8
// speedup vs baseline: 1.6028x; 1.0337x over previous
#include <cuda_runtime.h>
#include <cuda_fp16.h>

#define NLAT_IN  181
#define NLON_IN  360
#define NLAT_OUT 361
#define NLON_OUT 720
#define KSIZE    3
#define CIN      16
#define COUT     16
#define NNZ      8192
#define NBIN     (NLAT_OUT * 2)   // (hi, parity)
#define MAXB     128
#define NOH      (COUT / 2)       // 8 half2 channel-pairs
#define NWS      16               // sort warps
#define EPW      (NNZ / NWS)      // 512 elements per sort warp
#define NEIN     (NLAT_IN * KSIZE)       // 543 einsum blocks
#define SORT_SMEM ((NWS * NBIN + 768) * 4)

// Scratch (device globals; allocation is forbidden in kernel_launch)
__device__ __half2 d_xwh[KSIZE * NLAT_IN * NOH * NLON_IN]; // [k][tin][oh][w], 6.25 MB
__device__ int   d_meta[NNZ];          // (rowbase<<9) | s  (rowbase into d_xwh, s=p>>1)
__device__ float d_sval[NNZ];
__device__ int   d_pack[NNZ];          // bin<<16 | warp-local stable rank
__device__ int   d_offsets[NBIN + 1];

// ---------------------------------------------------------------------------
// Fused: blocks 0..542 do the channel-mix einsum; block 543 does the full
// stable counting sort (16 worker warps, 768 threads for the 722-bin scan).
__global__ void __launch_bounds__(768)
k_prep(const float* __restrict__ x, const float* __restrict__ wgt,
       const int* __restrict__ ker_idx, const int* __restrict__ row_idx,
       const int* __restrict__ col_idx, const float* __restrict__ vals) {
    int t = threadIdx.x;

    if (blockIdx.x == NEIN) {
        // ---------------- sort path ----------------
        extern __shared__ int swh[];      // [NWS][NBIN] counts, then [768] scan
        int* s = swh + NWS * NBIN;
        int w = t >> 5, lane = t & 31;

        for (int i = t; i < NWS * NBIN; i += 768) swh[i] = 0;
        __syncthreads();

        // Phase 1: per-warp stable ranks; spill (bin, rank) to d_pack
        if (w < NWS) {
            for (int r = 0; r < EPW / 32; r++) {
                int i   = w * EPW + r * 32 + lane;
                int col = col_idx[i];
                int hi  = col / NLON_OUT;
                int p   = col - hi * NLON_OUT;
                int bin = hi * 2 + (p & 1);
                unsigned match = __match_any_sync(0xffffffffu, bin);
                int rl   = __popc(match & ((1u << lane) - 1u));
                int base = swh[w * NBIN + bin];
                d_pack[i] = (bin << 16) | (base + rl);
                __syncwarp();
                if (rl == 0) swh[w * NBIN + bin] = base + __popc(match);
                __syncwarp();
            }
        }
        __syncthreads();

        // Phase 2: per-bin warp prefix + cross-bin exclusive scan
        int total = 0;
        if (t < NBIN) {
            int run = 0;
#pragma unroll
            for (int ww = 0; ww < NWS; ww++) {
                int v = swh[ww * NBIN + t];
                swh[ww * NBIN + t] = run;
                run += v;
            }
            total = run;
        }
        s[t] = total;
        __syncthreads();
        for (int d = 1; d < 768; d <<= 1) {
            int v = (t >= d) ? s[t - d] : 0;
            __syncthreads();
            s[t] += v;
            __syncthreads();
        }
        if (t < NBIN) {
            int excl = s[t] - total;
            d_offsets[t] = excl;
            if (t == NBIN - 1) d_offsets[NBIN] = excl + total;
#pragma unroll
            for (int ww = 0; ww < NWS; ww++) swh[ww * NBIN + t] += excl;
        }
        __syncthreads();

        // Phase 3: scatter; meta carries the precomputed xw row base
        if (w < NWS) {
            for (int r = 0; r < EPW / 32; r++) {
                int i    = w * EPW + r * 32 + lane;
                int pk   = d_pack[i];
                int bin  = pk >> 16;
                int rank = pk & 0xffff;
                int col  = col_idx[i];
                int hi   = col / NLON_OUT;
                int p    = col - hi * NLON_OUT;
                int pos  = swh[w * NBIN + bin] + rank;
                int rowbase = (ker_idx[i] * NLAT_IN + row_idx[i]) * (NOH * NLON_IN);
                d_meta[pos] = (rowbase << 9) | (p >> 1);
                d_sval[pos] = vals[i];
            }
        }
        return;
    }

    // ---------------- einsum path ----------------
    __shared__ float sw[COUT * CIN];  // [o][c] for this k
    int b   = blockIdx.x;
    int tin = b % NLAT_IN;
    int k   = b / NLAT_IN;
    if (t < COUT * CIN) sw[t] = wgt[t * KSIZE + k];  // wgt[o][c][k]
    __syncthreads();

    int h = (t >= 384) ? 1 : 0;
    int w = t - h * 384;
    if (w >= NLON_IN) return;

    float acc[8];
#pragma unroll
    for (int o = 0; o < 8; o++) acc[o] = 0.f;

#pragma unroll
    for (int c = 0; c < CIN; c++) {
        float xc = x[(c * NLAT_IN + tin) * NLON_IN + w];
#pragma unroll
        for (int o = 0; o < 8; o++)
            acc[o] += xc * sw[(h * 8 + o) * CIN + c];
    }
    __half2* dst = d_xwh + ((k * NLAT_IN + tin) * NOH + h * 4) * NLON_IN + w;
#pragma unroll
    for (int oh = 0; oh < 4; oh++)
        dst[oh * NLON_IN] = __floats2half2_rn(acc[2 * oh], acc[2 * oh + 1]);
}

// ---------------------------------------------------------------------------
// main gather: one block per (bin, channel-half). Thread jj owns lon q+2*jj
// for 8 output channels. Entry loop unrolled x4: 16 loads in flight.
__global__ void __launch_bounds__(384)
k_main(const float* __restrict__ bias, float* __restrict__ out) {
    __shared__ int   smeta[MAXB];
    __shared__ float sv[MAXB];
    int bb = blockIdx.x;
    int b  = bb >> 1;          // bin
    int h  = bb & 1;           // channel half
    int hi = b >> 1;
    int q  = b & 1;
    int tid = threadIdx.x;
    int beg = d_offsets[b];
    int cnt = d_offsets[b + 1] - beg;
    if (cnt > MAXB) cnt = MAXB;
    if (tid < cnt) {
        smeta[tid] = d_meta[beg + tid];
        sv[tid]    = d_sval[beg + tid];
    }
    __syncthreads();

    int jj = tid;
    if (jj >= NLON_IN) return;

    const int h4 = h * 4 * NLON_IN;   // offset to this half's oh group
    float acc[8];
#pragma unroll
    for (int o = 0; o < 8; o++) acc[o] = 0.f;

    int e = 0;
    for (; e + 3 < cnt; e += 4) {
        __half2 rg[4][4];
        float   vv[4];
#pragma unroll
        for (int u = 0; u < 4; u++) {
            int m = smeta[e + u];
            vv[u] = sv[e + u];
            int s = m & 511;
            int w = jj - s; if (w < 0) w += NLON_IN;
            const __half2* p = d_xwh + (m >> 9) + h4 + w;
#pragma unroll
            for (int oh = 0; oh < 4; oh++) rg[u][oh] = p[oh * NLON_IN];
        }
#pragma unroll
        for (int u = 0; u < 4; u++) {
            float v = vv[u];
#pragma unroll
            for (int oh = 0; oh < 4; oh++) {
                float2 f = __half22float2(rg[u][oh]);
                acc[2 * oh]     += v * f.x;
                acc[2 * oh + 1] += v * f.y;
            }
        }
    }
    for (; e < cnt; e++) {
        int m = smeta[e];
        float v = sv[e];
        int s = m & 511;
        int w = jj - s; if (w < 0) w += NLON_IN;
        const __half2* p = d_xwh + (m >> 9) + h4 + w;
#pragma unroll
        for (int oh = 0; oh < 4; oh++) {
            float2 f = __half22float2(p[oh * NLON_IN]);
            acc[2 * oh]     += v * f.x;
            acc[2 * oh + 1] += v * f.y;
        }
    }

    int lon = q + 2 * jj;
    const int cs = NLAT_OUT * NLON_OUT;
    float* dst = out + (h * 8) * cs + hi * NLON_OUT + lon;
#pragma unroll
    for (int o = 0; o < 8; o++) dst[o * cs] = acc[o] + bias[h * 8 + o];
}

// ---------------------------------------------------------------------------
extern "C" void kernel_launch(void* const* d_in, const int* in_sizes, int n_in,
                              void* d_out, int out_size) {
    const float* x       = (const float*)d_in[0];
    const float* weight  = (const float*)d_in[1];
    const float* bias    = (const float*)d_in[2];
    const int*   ker_idx = (const int*)d_in[3];
    const int*   row_idx = (const int*)d_in[4];
    const int*   col_idx = (const int*)d_in[5];
    const float* vals    = (const float*)d_in[6];
    float* out = (float*)d_out;

    (void)in_sizes; (void)n_in; (void)out_size;

    cudaFuncSetAttribute(k_prep, cudaFuncAttributeMaxDynamicSharedMemorySize,
                         SORT_SMEM);
    k_prep<<<NEIN + 1, 768, SORT_SMEM>>>(x, weight, ker_idx, row_idx,
                                         col_idx, vals);
    k_main<<<NBIN * 2, 384>>>(bias, out);
}

// round 9
// speedup vs baseline: 1.8489x; 1.1536x over previous
#include <cuda_runtime.h>
#include <cuda_fp16.h>

#define NLAT_IN  181
#define NLON_IN  360
#define NLAT_OUT 361
#define NLON_OUT 720
#define KSIZE    3
#define CIN      16
#define COUT     16
#define NNZ      8192
#define NBIN     (NLAT_OUT * 2)   // (hi, parity)
#define MAXB     128
#define NWS      16               // sort warps
#define EPW      (NNZ / NWS)      // 512 elements per sort warp
#define NEIN     (NLAT_IN * KSIZE)       // 543 einsum blocks
#define SORT_SMEM ((NWS * NBIN + 768) * 4)
#define NROW     (KSIZE * NLAT_IN)       // 543 xw rows

// xw: [row][h][w] as uint4 (8 fp16 channels packed). 543*2*360*16B = 6.25MB
__device__ uint4 d_xw4[NROW * 2 * NLON_IN];
__device__ int2  d_ent[NNZ];           // {meta, val-bits}; meta=(row*720)<<9 | s
__device__ int   d_pack[NNZ];          // bin<<16 | warp-local stable rank
__device__ int   d_offsets[NBIN + 1];

// ---------------------------------------------------------------------------
// Fused: blocks 0..542 do the channel-mix einsum; block 543 does the full
// stable counting sort (16 worker warps, 768 threads for the 722-bin scan).
__global__ void __launch_bounds__(768)
k_prep(const float* __restrict__ x, const float* __restrict__ wgt,
       const int* __restrict__ ker_idx, const int* __restrict__ row_idx,
       const int* __restrict__ col_idx, const float* __restrict__ vals) {
    int t = threadIdx.x;

    if (blockIdx.x == NEIN) {
        // ---------------- sort path ----------------
        extern __shared__ int swh[];      // [NWS][NBIN] counts, then [768] scan
        int* s = swh + NWS * NBIN;
        int w = t >> 5, lane = t & 31;

        for (int i = t; i < NWS * NBIN; i += 768) swh[i] = 0;
        __syncthreads();

        // Phase 1: per-warp stable ranks; spill (bin, rank) to d_pack
        if (w < NWS) {
            for (int r = 0; r < EPW / 32; r++) {
                int i   = w * EPW + r * 32 + lane;
                int col = col_idx[i];
                int hi  = col / NLON_OUT;
                int p   = col - hi * NLON_OUT;
                int bin = hi * 2 + (p & 1);
                unsigned match = __match_any_sync(0xffffffffu, bin);
                int rl   = __popc(match & ((1u << lane) - 1u));
                int base = swh[w * NBIN + bin];
                d_pack[i] = (bin << 16) | (base + rl);
                __syncwarp();
                if (rl == 0) swh[w * NBIN + bin] = base + __popc(match);
                __syncwarp();
            }
        }
        __syncthreads();

        // Phase 2: per-bin warp prefix + cross-bin exclusive scan
        int total = 0;
        if (t < NBIN) {
            int run = 0;
#pragma unroll
            for (int ww = 0; ww < NWS; ww++) {
                int v = swh[ww * NBIN + t];
                swh[ww * NBIN + t] = run;
                run += v;
            }
            total = run;
        }
        s[t] = total;
        __syncthreads();
        for (int d = 1; d < 768; d <<= 1) {
            int v = (t >= d) ? s[t - d] : 0;
            __syncthreads();
            s[t] += v;
            __syncthreads();
        }
        if (t < NBIN) {
            int excl = s[t] - total;
            d_offsets[t] = excl;
            if (t == NBIN - 1) d_offsets[NBIN] = excl + total;
#pragma unroll
            for (int ww = 0; ww < NWS; ww++) swh[ww * NBIN + t] += excl;
        }
        __syncthreads();

        // Phase 3: scatter; meta carries precomputed uint4 row offset
        if (w < NWS) {
            for (int r = 0; r < EPW / 32; r++) {
                int i    = w * EPW + r * 32 + lane;
                int pk   = d_pack[i];
                int bin  = pk >> 16;
                int rank = pk & 0xffff;
                int col  = col_idx[i];
                int hi   = col / NLON_OUT;
                int p    = col - hi * NLON_OUT;
                int pos  = swh[w * NBIN + bin] + rank;
                int row4 = (ker_idx[i] * NLAT_IN + row_idx[i]) * (2 * NLON_IN);
                d_ent[pos] = make_int2((row4 << 9) | (p >> 1),
                                       __float_as_int(vals[i]));
            }
        }
        return;
    }

    // ---------------- einsum path ----------------
    // block b: tin = b % 181, k = b / 181. h=0: ch 0..7, h=1: ch 8..15.
    __shared__ float sw[COUT * CIN];  // [o][c] for this k
    int b   = blockIdx.x;
    int tin = b % NLAT_IN;
    int k   = b / NLAT_IN;
    if (t < COUT * CIN) sw[t] = wgt[t * KSIZE + k];  // wgt[o][c][k]
    __syncthreads();

    int h = (t >= 384) ? 1 : 0;
    int w = t - h * 384;
    if (w >= NLON_IN) return;

    float acc[8];
#pragma unroll
    for (int o = 0; o < 8; o++) acc[o] = 0.f;

#pragma unroll
    for (int c = 0; c < CIN; c++) {
        float xc = x[(c * NLAT_IN + tin) * NLON_IN + w];
#pragma unroll
        for (int o = 0; o < 8; o++)
            acc[o] += xc * sw[(h * 8 + o) * CIN + c];
    }
    __half2 p0 = __floats2half2_rn(acc[0], acc[1]);
    __half2 p1 = __floats2half2_rn(acc[2], acc[3]);
    __half2 p2 = __floats2half2_rn(acc[4], acc[5]);
    __half2 p3 = __floats2half2_rn(acc[6], acc[7]);
    uint4 val;
    val.x = *(unsigned*)&p0;
    val.y = *(unsigned*)&p1;
    val.z = *(unsigned*)&p2;
    val.w = *(unsigned*)&p3;
    d_xw4[(k * NLAT_IN + tin) * (2 * NLON_IN) + h * NLON_IN + w] = val;
}

// ---------------------------------------------------------------------------
// main gather: one block per (bin, channel-half). Thread jj owns lon q+2*jj
// for 8 channels via ONE uint4 (LDG.128) per entry. Unrolled x4 for MLP.
__global__ void __launch_bounds__(384)
k_main(const float* __restrict__ bias, float* __restrict__ out) {
    __shared__ int2 se[MAXB];
    int bb = blockIdx.x;
    int b  = bb >> 1;          // bin
    int h  = bb & 1;           // channel half
    int hi = b >> 1;
    int q  = b & 1;
    int tid = threadIdx.x;
    int beg = d_offsets[b];
    int cnt = d_offsets[b + 1] - beg;
    if (cnt > MAXB) cnt = MAXB;
    if (tid < cnt) se[tid] = d_ent[beg + tid];
    __syncthreads();

    int jj = tid;
    if (jj >= NLON_IN) return;

    const uint4* __restrict__ xbase = d_xw4 + h * NLON_IN;
    float acc[8];
#pragma unroll
    for (int o = 0; o < 8; o++) acc[o] = 0.f;

    int e = 0;
    for (; e + 3 < cnt; e += 4) {
        uint4 dd[4];
        float vv[4];
#pragma unroll
        for (int u = 0; u < 4; u++) {
            int2 ev = se[e + u];
            vv[u] = __int_as_float(ev.y);
            int s = ev.x & 511;
            int w = jj - s; if (w < 0) w += NLON_IN;
            dd[u] = xbase[(ev.x >> 9) + w];
        }
#pragma unroll
        for (int u = 0; u < 4; u++) {
            float v = vv[u];
            float2 f0 = __half22float2(*(const __half2*)&dd[u].x);
            float2 f1 = __half22float2(*(const __half2*)&dd[u].y);
            float2 f2 = __half22float2(*(const __half2*)&dd[u].z);
            float2 f3 = __half22float2(*(const __half2*)&dd[u].w);
            acc[0] += v * f0.x; acc[1] += v * f0.y;
            acc[2] += v * f1.x; acc[3] += v * f1.y;
            acc[4] += v * f2.x; acc[5] += v * f2.y;
            acc[6] += v * f3.x; acc[7] += v * f3.y;
        }
    }
    for (; e < cnt; e++) {
        int2 ev = se[e];
        float v = __int_as_float(ev.y);
        int s = ev.x & 511;
        int w = jj - s; if (w < 0) w += NLON_IN;
        uint4 dd = xbase[(ev.x >> 9) + w];
        float2 f0 = __half22float2(*(const __half2*)&dd.x);
        float2 f1 = __half22float2(*(const __half2*)&dd.y);
        float2 f2 = __half22float2(*(const __half2*)&dd.z);
        float2 f3 = __half22float2(*(const __half2*)&dd.w);
        acc[0] += v * f0.x; acc[1] += v * f0.y;
        acc[2] += v * f1.x; acc[3] += v * f1.y;
        acc[4] += v * f2.x; acc[5] += v * f2.y;
        acc[6] += v * f3.x; acc[7] += v * f3.y;
    }

    int lon = q + 2 * jj;
    const int cs = NLAT_OUT * NLON_OUT;
    float* dst = out + (h * 8) * cs + hi * NLON_OUT + lon;
#pragma unroll
    for (int o = 0; o < 8; o++) dst[o * cs] = acc[o] + bias[h * 8 + o];
}

// ---------------------------------------------------------------------------
extern "C" void kernel_launch(void* const* d_in, const int* in_sizes, int n_in,
                              void* d_out, int out_size) {
    const float* x       = (const float*)d_in[0];
    const float* weight  = (const float*)d_in[1];
    const float* bias    = (const float*)d_in[2];
    const int*   ker_idx = (const int*)d_in[3];
    const int*   row_idx = (const int*)d_in[4];
    const int*   col_idx = (const int*)d_in[5];
    const float* vals    = (const float*)d_in[6];
    float* out = (float*)d_out;

    (void)in_sizes; (void)n_in; (void)out_size;

    cudaFuncSetAttribute(k_prep, cudaFuncAttributeMaxDynamicSharedMemorySize,
                         SORT_SMEM);
    k_prep<<<NEIN + 1, 768, SORT_SMEM>>>(x, weight, ker_idx, row_idx,
                                         col_idx, vals);
    k_main<<<NBIN * 2, 384>>>(bias, out);
}